// round 2
// baseline (speedup 1.0000x reference)
#include <cuda_runtime.h>
#include <cstdint>

#define N_NODES     200000
#define N_CLS       10
#define IDS_PER_CLS 20000
#define CENTER_BUDGET 2000
#define HOP_BUDGET  16384
#define CAND_CAP    8192   // hop boundary-bucket candidate capacity
#define CCAP        4096   // center candidate capacity (and #buckets)

// ---------------------------------------------------------------------------
// Scratch (device globals — no allocations allowed)
// ---------------------------------------------------------------------------
struct Ctrl {
  unsigned keys[6];    // k_cls(0,1), k_h1(2,3), k_h2(4,5)
  unsigned nonzero;    // # finite candidate keys this hop
  unsigned cand_n;     // boundary-bucket candidate count
  unsigned need2;      // remaining winners to pick from boundary bucket
  unsigned thrT;       // threshold digit
  unsigned take_all;   // boundary bucket entirely selected
  int      is64;       // edge_index dtype: 1 = int64, 0 = int32
};

__device__ Ctrl               g_ctrl;
__device__ float              g_probs[N_NODES];
__device__ unsigned long long g_keys[N_NODES];
__device__ unsigned char      g_center[N_NODES];
__device__ unsigned char      g_retained[N_NODES];
__device__ unsigned char      g_nbr[N_NODES];
__device__ unsigned           g_hist[65536];
__device__ unsigned long long g_cand[CAND_CAP];
__device__ int                g_center_nodes[N_CLS * CENTER_BUDGET];

// ---------------------------------------------------------------------------
// threefry2x32 — matches JAX bit-for-bit
// ---------------------------------------------------------------------------
__device__ __forceinline__ void tf2x32(unsigned k0, unsigned k1,
                                       unsigned x0, unsigned x1,
                                       unsigned &o0, unsigned &o1) {
  unsigned ks2 = k0 ^ k1 ^ 0x1BD11BDAu;
  x0 += k0; x1 += k1;
#define TFR(r) { x0 += x1; x1 = (x1 << (r)) | (x1 >> (32 - (r))); x1 ^= x0; }
  TFR(13) TFR(15) TFR(26) TFR(6)
  x0 += k1;  x1 += ks2 + 1u;
  TFR(17) TFR(29) TFR(16) TFR(24)
  x0 += ks2; x1 += k0 + 2u;
  TFR(13) TFR(15) TFR(26) TFR(6)
  x0 += k0;  x1 += k1 + 3u;
  TFR(17) TFR(29) TFR(16) TFR(24)
  x0 += k1;  x1 += ks2 + 4u;
  TFR(13) TFR(15) TFR(26) TFR(6)
  x0 += ks2; x1 += k0 + 5u;
#undef TFR
  o0 = x0; o1 = x1;
}

// partitionable threefry: 32-bit bits for flat index i (counter hi=0, lo=i)
__device__ __forceinline__ unsigned pbits32(unsigned k0, unsigned k1, unsigned i) {
  unsigned o0, o1;
  tf2x32(k0, k1, 0u, i, o0, o1);
  return o0 ^ o1;                               // fold
}
// partitionable threefry: 64-bit bits for flat index i
__device__ __forceinline__ unsigned long long pbits64(unsigned k0, unsigned k1, unsigned i) {
  unsigned o0, o1;
  tf2x32(k0, k1, 0u, i, o0, o1);
  return (((unsigned long long)o0) << 32) | o1;
}

extern __shared__ unsigned char s_raw[];

// ---------------------------------------------------------------------------
// init: dtype detection + key splits.
// Partitionable (foldlike) split: key_i = threefry((0,42), x0=0, x1=i) pair.
// ---------------------------------------------------------------------------
__global__ void k_init(const void* edge, long long E) {
  // int32 data reinterpreted as int64 yields out-of-range values almost surely.
  const long long* p = (const long long*)edge;
  int ok = 1;
  long long lim = (E < 128) ? E : 128;
  for (long long i = 0; i < lim; i++) {
    long long v = p[i];
    if (v < 0 || v >= N_NODES) { ok = 0; break; }
  }
  g_ctrl.is64 = ok;
  unsigned o0, o1;
  tf2x32(0u, 42u, 0u, 0u, o0, o1); g_ctrl.keys[0] = o0; g_ctrl.keys[1] = o1;  // k_cls
  tf2x32(0u, 42u, 0u, 1u, o0, o1); g_ctrl.keys[2] = o0; g_ctrl.keys[3] = o1;  // k_h1
  tf2x32(0u, 42u, 0u, 2u, o0, o1); g_ctrl.keys[4] = o0; g_ctrl.keys[5] = o1;  // k_h2
}

__global__ void k_zero() {
  int i = blockIdx.x * blockDim.x + threadIdx.x;
  if (i < N_NODES) {
    g_probs[i] = 0.f; g_center[i] = 0; g_retained[i] = 0; g_nbr[i] = 0;
  }
}

// ---------------------------------------------------------------------------
// Center sampling: uniform(k_cls, (10,20000)); stable argsort; first 2000.
// One block per class. Partitionable bit streams, flat index m = c*20000+j:
//  x64 on : f64 bits = pbits64(m); u = ((bits>>12)) * 2^-52
//  x64 off: f32 bits = pbits32(m); u = (bits>>9) * 2^-23; tie -> smaller j
// ---------------------------------------------------------------------------
__global__ __launch_bounds__(1024) void k_centers() {
  unsigned long long* skey = (unsigned long long*)s_raw;       // CCAP * 8
  unsigned*           sidx = (unsigned*)(skey + CCAP);         // CCAP * 4
  unsigned*           hist = sidx + CCAP;                      // CCAP * 4
  __shared__ unsigned s_cnt;
  __shared__ int      s_T;
  __shared__ unsigned part[1024];

  int c = blockIdx.x, tid = threadIdx.x;
  int is64 = g_ctrl.is64;
  unsigned kc0 = g_ctrl.keys[0], kc1 = g_ctrl.keys[1];

  for (int b = tid; b < CCAP; b += 1024) hist[b] = 0;
  if (tid == 0) s_cnt = 0;
  __syncthreads();

  for (int j = tid; j < IDS_PER_CLS; j += 1024) {
    unsigned m = (unsigned)(c * IDS_PER_CLS + j);
    unsigned long long key; unsigned b;
    if (is64) {
      unsigned long long mant = pbits64(kc0, kc1, m) >> 12;   // u = mant * 2^-52
      key = mant;
      b = (unsigned)(mant >> 40);
    } else {
      unsigned man = pbits32(kc0, kc1, m) >> 9;               // u = man * 2^-23
      key = (((unsigned long long)man) << 32) | (unsigned)j;  // tie -> smaller j
      b = man >> 11;
    }
    g_keys[m] = key;
    atomicAdd(&hist[b], 1u);
  }
  __syncthreads();

  // ascending threshold: smallest T with cum(<=T) >= 2000
  unsigned ps = 0;
  for (int b = tid * 4; b < tid * 4 + 4; b++) ps += hist[b];
  part[tid] = ps;
  __syncthreads();
  if (tid == 0) {
    unsigned acc = 0; int T = CCAP - 1;
    for (int t = 0; t < 1024; t++) {
      if (acc + part[t] >= CENTER_BUDGET) {
        for (int b = t * 4; b < t * 4 + 4; b++) {
          acc += hist[b];
          if (acc >= CENTER_BUDGET) { T = b; break; }
        }
        break;
      }
      acc += part[t];
    }
    s_T = T;
  }
  __syncthreads();
  int T = s_T;

  // collect candidates with bucket <= T
  for (int j = tid; j < IDS_PER_CLS; j += 1024) {
    int m = c * IDS_PER_CLS + j;
    unsigned long long key = g_keys[m];
    unsigned b = is64 ? (unsigned)(key >> 40) : (unsigned)(key >> 43);
    if ((int)b <= T) {
      unsigned pos = atomicAdd(&s_cnt, 1u);
      if (pos < CCAP) { skey[pos] = key; sidx[pos] = (unsigned)j; }
    }
  }
  __syncthreads();
  unsigned cnt = (s_cnt < CCAP) ? s_cnt : CCAP;
  for (int p = tid; p < CCAP; p += 1024)
    if (p >= (int)cnt) skey[p] = 0xFFFFFFFFFFFFFFFFULL;
  __syncthreads();

  // bitonic ascending on (skey, sidx)
  for (int k = 2; k <= CCAP; k <<= 1) {
    for (int j2 = k >> 1; j2 > 0; j2 >>= 1) {
      for (int i = tid; i < CCAP; i += 1024) {
        int ixj = i ^ j2;
        if (ixj > i) {
          bool up = ((i & k) == 0);
          unsigned long long a = skey[i], bb = skey[ixj];
          if ((a > bb) == up) {
            skey[i] = bb; skey[ixj] = a;
            unsigned t = sidx[i]; sidx[i] = sidx[ixj]; sidx[ixj] = t;
          }
        }
      }
      __syncthreads();
    }
  }

  for (int r = tid; r < CENTER_BUDGET; r += 1024) {
    int j = (int)sidx[r];
    int node = c * IDS_PER_CLS + j;      // ids_per_cls == arange
    g_center_nodes[c * CENTER_BUDGET + r] = node;
    g_center[node] = 1;
    g_retained[node] = 1;
  }
}

// ---------------------------------------------------------------------------
// Fused edge pass: degree segment-sum + neighbor mask (center already done).
// ---------------------------------------------------------------------------
__global__ void k_edges(const void* edge, const float* w, long long E) {
  long long i = (long long)blockIdx.x * blockDim.x + threadIdx.x;
  if (i >= E) return;
  int s, d;
  if (g_ctrl.is64) {
    const long long* p = (const long long*)edge;
    s = (int)p[i]; d = (int)p[E + i];
  } else {
    const int* p = (const int*)edge;
    s = p[i]; d = p[E + i];
  }
  atomicAdd(&g_probs[d], w[i]);
  if (g_center[s]) g_nbr[d] = 1;
}

__global__ void k_prep() {
  int i = blockIdx.x * blockDim.x + threadIdx.x;
  if (i < 65536) g_hist[i] = 0;
  if (i == 0) { g_ctrl.nonzero = 0; g_ctrl.cand_n = 0; }
}

// ---------------------------------------------------------------------------
// Hop keys: gumbel(k_h, (N,), f32), partitionable bits = pbits32(n):
//   u_raw = bitcast((bits>>9)|0x3f800000) - 1 ; u = max(tiny, u_raw + tiny)
//   g = -log(-log(u)) ; key_val = log(probs) + g
// Selection key64 = ord(key_val)<<32 | (0xFFFFFFFF - n)  (value desc, idx asc)
// ---------------------------------------------------------------------------
__global__ __launch_bounds__(1024) void k_build(int h) {
  int n = blockIdx.x * blockDim.x + threadIdx.x;
  unsigned long long kk = 0;
  if (n < N_NODES) {
    unsigned kh0 = g_ctrl.keys[2 + 2 * h], kh1 = g_ctrl.keys[3 + 2 * h];
    unsigned bits = pbits32(kh0, kh1, (unsigned)n);
    float ur = __uint_as_float((bits >> 9) | 0x3f800000u) - 1.0f;
    float u  = fmaxf(1.17549435e-38f, ur + 1.17549435e-38f);
    float g  = -logf(-logf(u));
    float v  = logf(g_probs[n]) + g;
    bool cand = g_nbr[n] && !g_retained[n];
    if (cand && isfinite(v)) {
      unsigned b   = __float_as_uint(v);
      unsigned ord = b ^ ((b & 0x80000000u) ? 0xFFFFFFFFu : 0x80000000u);
      kk = (((unsigned long long)ord) << 32) | (0xFFFFFFFFu - (unsigned)n);
      atomicAdd(&g_hist[(unsigned)(kk >> 48)], 1u);
    }
    g_keys[n] = kk;
  }
  unsigned act = __ballot_sync(0xFFFFFFFFu, kk != 0ULL);
  if ((threadIdx.x & 31) == 0 && act)
    atomicAdd(&g_ctrl.nonzero, (unsigned)__popc(act));
}

__global__ __launch_bounds__(1024) void k_thresh() {
  __shared__ unsigned part[1024];
  int tid = threadIdx.x;
  unsigned ps = 0;
  for (int b = tid * 64; b < tid * 64 + 64; b++) ps += g_hist[b];
  part[tid] = ps;
  __syncthreads();
  if (tid == 0) {
    unsigned nz = g_ctrl.nonzero;
    unsigned need = (nz < HOP_BUDGET) ? nz : HOP_BUDGET;
    unsigned acc = 0, above = 0; int T = 0;
    for (int t = 1023; t >= 0; t--) {
      if (acc + part[t] >= need) {
        for (int b = t * 64 + 63; b >= t * 64; b--) {
          if (acc + g_hist[b] >= need) { T = b; above = acc; break; }
          acc += g_hist[b];
        }
        break;
      }
      acc += part[t];
    }
    g_ctrl.thrT = (unsigned)T;
    unsigned need2 = need - above;
    g_ctrl.need2 = need2;
    g_ctrl.take_all = (need2 >= g_hist[T]) ? 1u : 0u;
    g_ctrl.cand_n = 0;
  }
}

__global__ void k_scatter() {
  int n = blockIdx.x * blockDim.x + threadIdx.x;
  if (n >= N_NODES) return;
  unsigned long long kk = g_keys[n];
  if (!kk) return;
  unsigned d = (unsigned)(kk >> 48);
  unsigned T = g_ctrl.thrT;
  if (d > T) {
    g_retained[n] = 1;
  } else if (d == T) {
    if (g_ctrl.take_all) {
      g_retained[n] = 1;
    } else {
      unsigned pos = atomicAdd(&g_ctrl.cand_n, 1u);
      if (pos < CAND_CAP) g_cand[pos] = kk;
    }
  }
}

__global__ __launch_bounds__(1024) void k_final() {
  unsigned long long* fkey = (unsigned long long*)s_raw;   // CAND_CAP * 8
  int tid = threadIdx.x;
  if (g_ctrl.take_all) return;
  unsigned cnt = g_ctrl.cand_n; if (cnt > CAND_CAP) cnt = CAND_CAP;
  unsigned need2 = g_ctrl.need2;
  if (need2 == 0) return;
  for (int i = tid; i < CAND_CAP; i += 1024)
    fkey[i] = (i < (int)cnt) ? g_cand[i] : 0ULL;
  __syncthreads();
  // bitonic descending
  for (int k = 2; k <= CAND_CAP; k <<= 1) {
    for (int j = k >> 1; j > 0; j >>= 1) {
      for (int i = tid; i < CAND_CAP; i += 1024) {
        int ixj = i ^ j;
        if (ixj > i) {
          bool up = ((i & k) == 0);
          unsigned long long a = fkey[i], b = fkey[ixj];
          if ((a < b) == up) { fkey[i] = b; fkey[ixj] = a; }
        }
      }
      __syncthreads();
    }
  }
  for (int r = tid; r < (int)need2; r += 1024) {
    unsigned n = 0xFFFFFFFFu - (unsigned)(fkey[r] & 0xFFFFFFFFu);
    g_retained[n] = 1;
  }
}

// ---------------------------------------------------------------------------
// Output: f32 [center_nodes | retained | masked_probs]; branch on out_size.
// ---------------------------------------------------------------------------
__global__ void k_out(float* out, long long out_size) {
  long long i = (long long)blockIdx.x * blockDim.x + threadIdx.x;
  if (i >= out_size) return;
  float v;
  if (out_size == 420000) {
    if (i < 20000)        v = (float)g_center_nodes[i];
    else if (i < 220000)  v = g_retained[i - 20000] ? 1.f : 0.f;
    else                  v = g_retained[i - 220000] ? g_probs[i - 220000] : 0.f;
  } else if (out_size == 400000) {
    if (i < 200000)       v = g_retained[i] ? 1.f : 0.f;
    else                  v = g_retained[i - 200000] ? g_probs[i - 200000] : 0.f;
  } else if (out_size == 200000) {
    v = g_retained[i] ? g_probs[i] : 0.f;
  } else if (out_size == 20000) {
    v = (float)g_center_nodes[i];
  } else {
    v = 0.f;
  }
  out[i] = v;
}

// ---------------------------------------------------------------------------
extern "C" void kernel_launch(void* const* d_in, const int* in_sizes, int n_in,
                              void* d_out, int out_size) {
  const void* edge = d_in[0];
  const float* w = (const float*)d_in[1];
  long long E = (long long)in_sizes[0] / 2;

  cudaFuncSetAttribute(k_centers, cudaFuncAttributeMaxDynamicSharedMemorySize,
                       CCAP * 8 + CCAP * 4 + CCAP * 4);
  cudaFuncSetAttribute(k_final, cudaFuncAttributeMaxDynamicSharedMemorySize,
                       CAND_CAP * 8);

  k_init<<<1, 1>>>(edge, E);
  k_zero<<<(N_NODES + 1023) / 1024, 1024>>>();
  k_centers<<<N_CLS, 1024, CCAP * 8 + CCAP * 4 + CCAP * 4>>>();
  k_edges<<<(unsigned)((E + 255) / 256), 256>>>(edge, w, E);
  for (int h = 0; h < 2; h++) {
    k_prep<<<64, 1024>>>();
    k_build<<<(N_NODES + 1023) / 1024, 1024>>>(h);
    k_thresh<<<1, 1024>>>();
    k_scatter<<<(N_NODES + 1023) / 1024, 1024>>>();
    k_final<<<1, 1024, CAND_CAP * 8>>>();
  }
  k_out<<<((long long)out_size + 255) / 256, 256>>>((float*)d_out, (long long)out_size);
}